// round 12
// baseline (speedup 1.0000x reference)
#include <cuda_runtime.h>
#include <stdint.h>
#include <math.h>

#define NB   64
#define TT   2048
#define DH   256
#define MTOT (NB * TT)

// ---------------------------------------------------------------------------
// XLA EmitFastTanh, with_fma=true variant (VERIFIED bit-exact vs reference):
// fused Horner, clamp +-7.99881172180175781, |x| < 0.0004 -> x, IEEE divide.
// ---------------------------------------------------------------------------
__device__ __forceinline__ float tanh_xla(float x) {
    float a  = fabsf(x);
    float xc = fminf(fmaxf(x, -7.99881172180175781f), 7.99881172180175781f);
    float x2 = xc * xc;
    float p = __fmaf_rn(x2, -2.76076847742355e-16f, 2.00018790482477e-13f);
    p = __fmaf_rn(x2, p, -8.60467152213735e-11f);
    p = __fmaf_rn(x2, p,  5.12229709037114e-08f);
    p = __fmaf_rn(x2, p,  1.48572235717979e-05f);
    p = __fmaf_rn(x2, p,  6.37261928875436e-04f);
    p = __fmaf_rn(x2, p,  4.89352455891786e-03f);
    p = xc * p;
    float q = __fmaf_rn(x2, 1.19825839466702e-06f, 1.18534705686654e-04f);
    q = __fmaf_rn(x2, q, 2.26843463243900e-03f);
    q = __fmaf_rn(x2, q, 4.89352518554385e-03f);
    float r = __fdiv_rn(p, q);
    return (a < 0.0004f) ? x : r;
}

// ===========================================================================
// Kernel A: out = X @ Wx + bx  (131072 x 256 x 256)
// Per-element: single sequential ascending FFMA chain + RN bias add.
// (VERIFIED bit-exact vs reference on probe batches.)
// ===========================================================================
__global__ void __launch_bounds__(256)
xproj_kernel(const float* __restrict__ X, const float* __restrict__ W,
             const float* __restrict__ bx, float* __restrict__ out)
{
    __shared__ float As[8][128];
    __shared__ float Bs[8][128];

    const int tid = threadIdx.x;
    const int bm = blockIdx.x * 128;
    const int bn = blockIdx.y * 128;
    const int tx = tid & 15, ty = tid >> 4;
    const int m0 = ty * 8, n0 = tx * 8;
    const int arow = tid >> 1, acol4 = (tid & 1) * 4;
    const int brow = tid >> 5, bcol4 = (tid & 31) * 4;

    float acc[8][8];
    #pragma unroll
    for (int i = 0; i < 8; i++)
        #pragma unroll
        for (int j = 0; j < 8; j++) acc[i][j] = 0.f;

    for (int k0 = 0; k0 < DH; k0 += 8) {
        float4 av = *(const float4*)&X[(size_t)(bm + arow) * DH + k0 + acol4];
        float4 bv = *(const float4*)&W[(size_t)(k0 + brow) * DH + bn + bcol4];
        __syncthreads();
        As[acol4 + 0][arow] = av.x; As[acol4 + 1][arow] = av.y;
        As[acol4 + 2][arow] = av.z; As[acol4 + 3][arow] = av.w;
        *(float4*)&Bs[brow][bcol4] = bv;
        __syncthreads();
        #pragma unroll
        for (int k = 0; k < 8; k++) {
            float a[8], b[8];
            *(float4*)(a)     = *(const float4*)&As[k][m0];
            *(float4*)(a + 4) = *(const float4*)&As[k][m0 + 4];
            *(float4*)(b)     = *(const float4*)&Bs[k][n0];
            *(float4*)(b + 4) = *(const float4*)&Bs[k][n0 + 4];
            #pragma unroll
            for (int i = 0; i < 8; i++)
                #pragma unroll
                for (int j = 0; j < 8; j++)
                    acc[i][j] = __fmaf_rn(a[i], b[j], acc[i][j]);
        }
    }
    float bxr[8];
    #pragma unroll
    for (int j = 0; j < 8; j++) bxr[j] = bx[bn + n0 + j];
    #pragma unroll
    for (int i = 0; i < 8; i++) {
        const size_t row = (size_t)(bm + m0 + i);
        #pragma unroll
        for (int j = 0; j < 8; j += 4) {
            float4 v;
            v.x = __fadd_rn(acc[i][j+0], bxr[j+0]);
            v.y = __fadd_rn(acc[i][j+1], bxr[j+1]);
            v.z = __fadd_rn(acc[i][j+2], bxr[j+2]);
            v.w = __fadd_rn(acc[i][j+3], bxr[j+3]);
            *(float4*)&out[row * DH + bn + n0 + j] = v;
        }
    }
}

// ===========================================================================
// Kernel B: recurrence. One CTA per batch (64 CTAs), 256 threads = 1/column.
// Numerics (VERIFIED): acc = sequential FFMA chain k=0..255 ascending;
// pre = (xp + acc) + bh (RN adds); h = tanh_xla(pre).
// Wh k=0..127 in registers (128/thread), k=128..255 in smem (128 KB).
// h double-buffered in smem -> ONE barrier per step. xp prefetched under
// the 1024-cycle FMA chain.
// ===========================================================================
#define REC_SMEM_BYTES ((128 * DH + 2 * DH) * 4)

__global__ void __launch_bounds__(256, 1)
rnn_rec_kernel(const float* __restrict__ Wh, const float* __restrict__ bh,
               const float* __restrict__ h_init, float* __restrict__ out)
{
    extern __shared__ float sm[];
    float* wS = sm;                 // [128][256]: Wh rows 128..255
    float* hA = sm + 128 * DH;      // [256]
    float* hB = hA + DH;            // [256]

    const int b = blockIdx.x;
    const int c = threadIdx.x;

    // Wh rows 0..127, column c -> registers (loads coalesced per k)
    float wreg[128];
    #pragma unroll
    for (int k = 0; k < 128; k++)
        wreg[k] = Wh[(size_t)k * DH + c];

    // Wh rows 128..255 -> smem [k][c] (per-k conflict-free across lanes)
    for (int k = 0; k < 128; k++)
        wS[k * DH + c] = Wh[(size_t)(128 + k) * DH + c];

    hA[c] = h_init[(size_t)b * DH + c];
    const float bias = bh[c];
    __syncthreads();

    float* hcur = hA;
    float* hnxt = hB;
    float* obase = out + (size_t)b * TT * DH + c;

    for (int t = 0; t < TT; t++) {
        // prefetch this step's x-projection (hidden under the FMA chain)
        float xp = obase[(size_t)t * DH];

        // single sequential FFMA chain, k ascending 0..255
        float acc = 0.f;
        #pragma unroll
        for (int k = 0; k < 128; k++)
            acc = __fmaf_rn(hcur[k], wreg[k], acc);
        #pragma unroll 32
        for (int k = 0; k < 128; k++)
            acc = __fmaf_rn(hcur[128 + k], wS[k * DH + c], acc);

        float pre = __fadd_rn(__fadd_rn(xp, acc), bias);
        float h = tanh_xla(pre);

        hnxt[c] = h;
        obase[(size_t)t * DH] = h;

        __syncthreads();   // hnxt complete; hcur free for reuse next step

        float* tmp = hcur; hcur = hnxt; hnxt = tmp;
    }
}

// ===========================================================================
extern "C" void kernel_launch(void* const* d_in, const int* in_sizes, int n_in,
                              void* d_out, int out_size)
{
    const float* seq_x  = (const float*)d_in[0];
    const float* Wx     = (const float*)d_in[1];
    const float* bx     = (const float*)d_in[2];
    const float* Wh     = (const float*)d_in[3];
    const float* bh     = (const float*)d_in[4];
    const float* h_init = (const float*)d_in[5];
    float* out = (float*)d_out;

    xproj_kernel<<<dim3(MTOT / 128, DH / 128), 256>>>(seq_x, Wx, bx, out);

    cudaFuncSetAttribute(rnn_rec_kernel,
                         cudaFuncAttributeMaxDynamicSharedMemorySize,
                         REC_SMEM_BYTES);
    rnn_rec_kernel<<<NB, 256, REC_SMEM_BYTES>>>(Wh, bh, h_init, out);
}

// round 13
// speedup vs baseline: 1.1300x; 1.1300x over previous
#include <cuda_runtime.h>
#include <stdint.h>
#include <math.h>

#define NB   64
#define TT   2048
#define DH   256
#define MTOT (NB * TT)

// ---------------------------------------------------------------------------
// XLA EmitFastTanh, with_fma=true (VERIFIED bit-exact): fused Horner,
// clamp +-7.99881172180175781, |x| < 0.0004 -> x, IEEE RN divide.
// ---------------------------------------------------------------------------
__device__ __forceinline__ float tanh_xla(float x) {
    float a  = fabsf(x);
    float xc = fminf(fmaxf(x, -7.99881172180175781f), 7.99881172180175781f);
    float x2 = xc * xc;
    float p = __fmaf_rn(x2, -2.76076847742355e-16f, 2.00018790482477e-13f);
    p = __fmaf_rn(x2, p, -8.60467152213735e-11f);
    p = __fmaf_rn(x2, p,  5.12229709037114e-08f);
    p = __fmaf_rn(x2, p,  1.48572235717979e-05f);
    p = __fmaf_rn(x2, p,  6.37261928875436e-04f);
    p = __fmaf_rn(x2, p,  4.89352455891786e-03f);
    p = xc * p;
    float q = __fmaf_rn(x2, 1.19825839466702e-06f, 1.18534705686654e-04f);
    q = __fmaf_rn(x2, q, 2.26843463243900e-03f);
    q = __fmaf_rn(x2, q, 4.89352518554385e-03f);
    float r = __fdiv_rn(p, q);
    return (a < 0.0004f) ? x : r;
}

// ===========================================================================
// Kernel A: out = X @ Wx + bx  (131072 x 256 x 256), bit-exact FFMA chain.
// Double-buffered smem: LDG of tile k+1 overlaps compute of tile k.
// ===========================================================================
__global__ void __launch_bounds__(256)
xproj_kernel(const float* __restrict__ X, const float* __restrict__ W,
             const float* __restrict__ bx, float* __restrict__ out)
{
    __shared__ float As[2][8][128];   // As[buf][k][m]
    __shared__ float Bs[2][8][128];   // Bs[buf][k][n]

    const int tid = threadIdx.x;
    const int bm = blockIdx.x * 128;
    const int bn = blockIdx.y * 128;
    const int tx = tid & 15, ty = tid >> 4;
    const int m0 = ty * 8, n0 = tx * 8;
    const int arow = tid >> 1, acol4 = (tid & 1) * 4;
    const int brow = tid >> 5, bcol4 = (tid & 31) * 4;

    float acc[8][8];
    #pragma unroll
    for (int i = 0; i < 8; i++)
        #pragma unroll
        for (int j = 0; j < 8; j++) acc[i][j] = 0.f;

    // preload tile 0
    float4 av = *(const float4*)&X[(size_t)(bm + arow) * DH + acol4];
    float4 bv = *(const float4*)&W[(size_t)brow * DH + bn + bcol4];
    As[0][acol4 + 0][arow] = av.x; As[0][acol4 + 1][arow] = av.y;
    As[0][acol4 + 2][arow] = av.z; As[0][acol4 + 3][arow] = av.w;
    *(float4*)&Bs[0][brow][bcol4] = bv;
    __syncthreads();

    #pragma unroll 4
    for (int it = 0; it < 32; it++) {
        const int cur = it & 1;
        if (it < 31) {
            const int k0 = (it + 1) * 8;
            av = *(const float4*)&X[(size_t)(bm + arow) * DH + k0 + acol4];
            bv = *(const float4*)&W[(size_t)(k0 + brow) * DH + bn + bcol4];
        }
        #pragma unroll
        for (int k = 0; k < 8; k++) {
            float a[8], b[8];
            *(float4*)(a)     = *(const float4*)&As[cur][k][m0];
            *(float4*)(a + 4) = *(const float4*)&As[cur][k][m0 + 4];
            *(float4*)(b)     = *(const float4*)&Bs[cur][k][n0];
            *(float4*)(b + 4) = *(const float4*)&Bs[cur][k][n0 + 4];
            #pragma unroll
            for (int i = 0; i < 8; i++)
                #pragma unroll
                for (int j = 0; j < 8; j++)
                    acc[i][j] = __fmaf_rn(a[i], b[j], acc[i][j]);
        }
        if (it < 31) {
            const int nxt = cur ^ 1;
            As[nxt][acol4 + 0][arow] = av.x; As[nxt][acol4 + 1][arow] = av.y;
            As[nxt][acol4 + 2][arow] = av.z; As[nxt][acol4 + 3][arow] = av.w;
            *(float4*)&Bs[nxt][brow][bcol4] = bv;
            __syncthreads();
        }
    }

    float bxr[8];
    #pragma unroll
    for (int j = 0; j < 8; j++) bxr[j] = bx[bn + n0 + j];
    #pragma unroll
    for (int i = 0; i < 8; i++) {
        const size_t row = (size_t)(bm + m0 + i);
        #pragma unroll
        for (int j = 0; j < 8; j += 4) {
            float4 v;
            v.x = __fadd_rn(acc[i][j+0], bxr[j+0]);
            v.y = __fadd_rn(acc[i][j+1], bxr[j+1]);
            v.z = __fadd_rn(acc[i][j+2], bxr[j+2]);
            v.w = __fadd_rn(acc[i][j+3], bxr[j+3]);
            *(float4*)&out[row * DH + bn + n0 + j] = v;
        }
    }
}

// ===========================================================================
// Kernel B: recurrence, bit-exact chain, software-pipelined operand fetch.
// One CTA per batch (64 CTAs), 256 threads = 1/column.
// Wh rows 0..127 in registers; rows 128..255 in smem TRANSPOSED wT[c][k]
// (stride 132 floats = 528 B: 16B-aligned, conflict-free float4 per lane).
// h broadcast-read as float4. Chain runs in chunks of 8 with operands
// prefetched one chunk (32 cyc) ahead of use.
// ===========================================================================
#define WT_STRIDE 132
#define REC_SMEM_BYTES ((256 * WT_STRIDE + 2 * DH) * 4)

__global__ void __launch_bounds__(256, 1)
rnn_rec_kernel(const float* __restrict__ Wh, const float* __restrict__ bh,
               const float* __restrict__ h_init, float* __restrict__ out)
{
    extern __shared__ float sm[];
    float* wT = sm;                       // [256][WT_STRIDE]
    float* hA = sm + 256 * WT_STRIDE;     // [256]
    float* hB = hA + DH;                  // [256]

    const int b = blockIdx.x;
    const int c = threadIdx.x;

    // Wh rows 0..127, column c -> registers (coalesced LDG per k)
    float wreg[128];
    #pragma unroll
    for (int k = 0; k < 128; k++)
        wreg[k] = Wh[(size_t)k * DH + c];

    // Wh rows 128..255 -> transposed smem wT[c][k]
    for (int k = 0; k < 128; k++)
        wT[c * WT_STRIDE + k] = Wh[(size_t)(128 + k) * DH + c];

    hA[c] = h_init[(size_t)b * DH + c];
    const float bias = bh[c];
    __syncthreads();

    float* hcur = hA;
    float* hnxt = hB;
    float* obase = out + (size_t)b * TT * DH + c;
    const float4* wt4 = (const float4*)(wT + c * WT_STRIDE);   // 33 float4s

    for (int t = 0; t < TT; t++) {
        // prefetch x-projection (hidden under the 1024-cycle chain)
        float xp = obase[(size_t)t * DH];

        const float4* h4 = (const float4*)hcur;

        float acc = 0.f;

        // --- part 1: k = 0..127, w in registers, h via pipelined LDS.128 ---
        float4 ha = h4[0], hb = h4[1];
        float4 wa = wt4[0], wb = wt4[1];     // preload part-2 w chunk 0
        #pragma unroll
        for (int ch = 0; ch < 16; ch++) {
            float4 hc, hd;
            if (ch < 15) { hc = h4[2 * ch + 2]; hd = h4[2 * ch + 3]; }
            else         { hc = h4[32];         hd = h4[33];         }
            const int kb = ch * 8;
            acc = __fmaf_rn(ha.x, wreg[kb + 0], acc);
            acc = __fmaf_rn(ha.y, wreg[kb + 1], acc);
            acc = __fmaf_rn(ha.z, wreg[kb + 2], acc);
            acc = __fmaf_rn(ha.w, wreg[kb + 3], acc);
            acc = __fmaf_rn(hb.x, wreg[kb + 4], acc);
            acc = __fmaf_rn(hb.y, wreg[kb + 5], acc);
            acc = __fmaf_rn(hb.z, wreg[kb + 6], acc);
            acc = __fmaf_rn(hb.w, wreg[kb + 7], acc);
            ha = hc; hb = hd;
        }

        // --- part 2: k = 128..255, h and w both pipelined LDS.128 ---
        #pragma unroll
        for (int ch = 0; ch < 16; ch++) {
            float4 hc, hd, wc, wd;
            if (ch < 15) {
                hc = h4[2 * ch + 34]; hd = h4[2 * ch + 35];
                wc = wt4[2 * ch + 2]; wd = wt4[2 * ch + 3];
            }
            acc = __fmaf_rn(ha.x, wa.x, acc);
            acc = __fmaf_rn(ha.y, wa.y, acc);
            acc = __fmaf_rn(ha.z, wa.z, acc);
            acc = __fmaf_rn(ha.w, wa.w, acc);
            acc = __fmaf_rn(hb.x, wb.x, acc);
            acc = __fmaf_rn(hb.y, wb.y, acc);
            acc = __fmaf_rn(hb.z, wb.z, acc);
            acc = __fmaf_rn(hb.w, wb.w, acc);
            ha = hc; hb = hd; wa = wc; wb = wd;
        }

        float pre = __fadd_rn(__fadd_rn(xp, acc), bias);
        float h = tanh_xla(pre);

        hnxt[c] = h;
        obase[(size_t)t * DH] = h;

        __syncthreads();

        float* tmp = hcur; hcur = hnxt; hnxt = tmp;
    }
}

// ===========================================================================
extern "C" void kernel_launch(void* const* d_in, const int* in_sizes, int n_in,
                              void* d_out, int out_size)
{
    const float* seq_x  = (const float*)d_in[0];
    const float* Wx     = (const float*)d_in[1];
    const float* bx     = (const float*)d_in[2];
    const float* Wh     = (const float*)d_in[3];
    const float* bh     = (const float*)d_in[4];
    const float* h_init = (const float*)d_in[5];
    float* out = (float*)d_out;

    xproj_kernel<<<dim3(MTOT / 128, DH / 128), 256>>>(seq_x, Wx, bx, out);

    cudaFuncSetAttribute(rnn_rec_kernel,
                         cudaFuncAttributeMaxDynamicSharedMemorySize,
                         REC_SMEM_BYTES);
    rnn_rec_kernel<<<NB, 256, REC_SMEM_BYTES>>>(Wh, bh, h_init, out);
}

// round 14
// speedup vs baseline: 1.3215x; 1.1695x over previous
#include <cuda_runtime.h>
#include <stdint.h>
#include <math.h>

#define NB   64
#define TT   2048
#define DH   256
#define MTOT (NB * TT)

// ---------------------------------------------------------------------------
// XLA EmitFastTanh, with_fma=true (VERIFIED bit-exact): fused Horner,
// clamp +-7.99881172180175781, |x| < 0.0004 -> x, IEEE RN divide.
// ---------------------------------------------------------------------------
__device__ __forceinline__ float tanh_xla(float x) {
    float a  = fabsf(x);
    float xc = fminf(fmaxf(x, -7.99881172180175781f), 7.99881172180175781f);
    float x2 = xc * xc;
    float p = __fmaf_rn(x2, -2.76076847742355e-16f, 2.00018790482477e-13f);
    p = __fmaf_rn(x2, p, -8.60467152213735e-11f);
    p = __fmaf_rn(x2, p,  5.12229709037114e-08f);
    p = __fmaf_rn(x2, p,  1.48572235717979e-05f);
    p = __fmaf_rn(x2, p,  6.37261928875436e-04f);
    p = __fmaf_rn(x2, p,  4.89352455891786e-03f);
    p = xc * p;
    float q = __fmaf_rn(x2, 1.19825839466702e-06f, 1.18534705686654e-04f);
    q = __fmaf_rn(x2, q, 2.26843463243900e-03f);
    q = __fmaf_rn(x2, q, 4.89352518554385e-03f);
    float r = __fdiv_rn(p, q);
    return (a < 0.0004f) ? x : r;
}

// ===========================================================================
// Kernel A: out = X @ Wx + bx  (131072 x 256 x 256), bit-exact FFMA chain.
// Double-buffered smem (unchanged from R12 — passing & adequate).
// ===========================================================================
__global__ void __launch_bounds__(256)
xproj_kernel(const float* __restrict__ X, const float* __restrict__ W,
             const float* __restrict__ bx, float* __restrict__ out)
{
    __shared__ float As[2][8][128];
    __shared__ float Bs[2][8][128];

    const int tid = threadIdx.x;
    const int bm = blockIdx.x * 128;
    const int bn = blockIdx.y * 128;
    const int tx = tid & 15, ty = tid >> 4;
    const int m0 = ty * 8, n0 = tx * 8;
    const int arow = tid >> 1, acol4 = (tid & 1) * 4;
    const int brow = tid >> 5, bcol4 = (tid & 31) * 4;

    float acc[8][8];
    #pragma unroll
    for (int i = 0; i < 8; i++)
        #pragma unroll
        for (int j = 0; j < 8; j++) acc[i][j] = 0.f;

    float4 av = *(const float4*)&X[(size_t)(bm + arow) * DH + acol4];
    float4 bv = *(const float4*)&W[(size_t)brow * DH + bn + bcol4];
    As[0][acol4 + 0][arow] = av.x; As[0][acol4 + 1][arow] = av.y;
    As[0][acol4 + 2][arow] = av.z; As[0][acol4 + 3][arow] = av.w;
    *(float4*)&Bs[0][brow][bcol4] = bv;
    __syncthreads();

    #pragma unroll 4
    for (int it = 0; it < 32; it++) {
        const int cur = it & 1;
        if (it < 31) {
            const int k0 = (it + 1) * 8;
            av = *(const float4*)&X[(size_t)(bm + arow) * DH + k0 + acol4];
            bv = *(const float4*)&W[(size_t)(k0 + brow) * DH + bn + bcol4];
        }
        #pragma unroll
        for (int k = 0; k < 8; k++) {
            float a[8], b[8];
            *(float4*)(a)     = *(const float4*)&As[cur][k][m0];
            *(float4*)(a + 4) = *(const float4*)&As[cur][k][m0 + 4];
            *(float4*)(b)     = *(const float4*)&Bs[cur][k][n0];
            *(float4*)(b + 4) = *(const float4*)&Bs[cur][k][n0 + 4];
            #pragma unroll
            for (int i = 0; i < 8; i++)
                #pragma unroll
                for (int j = 0; j < 8; j++)
                    acc[i][j] = __fmaf_rn(a[i], b[j], acc[i][j]);
        }
        if (it < 31) {
            const int nxt = cur ^ 1;
            As[nxt][acol4 + 0][arow] = av.x; As[nxt][acol4 + 1][arow] = av.y;
            As[nxt][acol4 + 2][arow] = av.z; As[nxt][acol4 + 3][arow] = av.w;
            *(float4*)&Bs[nxt][brow][bcol4] = bv;
            __syncthreads();
        }
    }

    float bxr[8];
    #pragma unroll
    for (int j = 0; j < 8; j++) bxr[j] = bx[bn + n0 + j];
    #pragma unroll
    for (int i = 0; i < 8; i++) {
        const size_t row = (size_t)(bm + m0 + i);
        #pragma unroll
        for (int j = 0; j < 8; j += 4) {
            float4 v;
            v.x = __fadd_rn(acc[i][j+0], bxr[j+0]);
            v.y = __fadd_rn(acc[i][j+1], bxr[j+1]);
            v.z = __fadd_rn(acc[i][j+2], bxr[j+2]);
            v.w = __fadd_rn(acc[i][j+3], bxr[j+3]);
            *(float4*)&out[row * DH + bn + n0 + j] = v;
        }
    }
}

// ===========================================================================
// Kernel B: recurrence. One CTA/batch, 256 thr = 1/column. Bit-exact chain:
// k ascending 0..255, (xp+acc)+bh, tanh_xla.
// Wh k=0..159 in registers (160/thread); k=160..255 transposed in smem
// (stride 100 floats: 100%32=4 -> conflict-free LDS.128 across lanes).
// Single regular 32-chunk pipeline, operands loaded 2 chunks (64 cyc) ahead.
// ===========================================================================
#define NREG       160
#define WT_STRIDE  100
#define REC_SMEM_BYTES ((256 * WT_STRIDE + 2 * DH) * 4)

__global__ void __launch_bounds__(256, 1)
rnn_rec_kernel(const float* __restrict__ Wh, const float* __restrict__ bh,
               const float* __restrict__ h_init, float* __restrict__ out)
{
    extern __shared__ float sm[];
    float* wT = sm;                       // [256][WT_STRIDE]: Wh rows 160..255
    float* hA = sm + 256 * WT_STRIDE;     // [256]
    float* hB = hA + DH;                  // [256]

    const int b = blockIdx.x;
    const int c = threadIdx.x;

    // Wh rows 0..159, column c -> registers (coalesced LDG per k)
    float wreg[NREG];
    #pragma unroll
    for (int k = 0; k < NREG; k++)
        wreg[k] = Wh[(size_t)k * DH + c];

    // Wh rows 160..255 -> transposed smem wT[c][0..95]
    #pragma unroll
    for (int k = 0; k < 96; k++)
        wT[c * WT_STRIDE + k] = Wh[(size_t)(NREG + k) * DH + c];

    hA[c] = h_init[(size_t)b * DH + c];
    const float bias = bh[c];
    __syncthreads();

    float* hcur = hA;
    float* hnxt = hB;
    float* obase = out + (size_t)b * TT * DH + c;
    const float4* wt4 = (const float4*)(wT + c * WT_STRIDE);   // 24 float4

    for (int t = 0; t < TT; t++) {
        float xp = obase[(size_t)t * DH];          // hidden under the chain

        const float4* h4 = (const float4*)hcur;

        // depth-2 pipeline preloads
        float4 h0 = h4[0], h1 = h4[1], h2 = h4[2], h3 = h4[3];
        float4 w0 = wt4[0], w1 = wt4[1], w2 = wt4[2], w3 = wt4[3];

        float acc = 0.f;

        #pragma unroll
        for (int ch = 0; ch < 32; ch++) {
            // prefetch chunk ch+2 (static conditions; fully unrolled)
            float4 hc, hd, wc, wd;
            if (ch < 30) { hc = h4[2 * ch + 4]; hd = h4[2 * ch + 5]; }
            if (ch >= 20 && ch < 30) {
                wc = wt4[(ch - 18) * 2];
                wd = wt4[(ch - 18) * 2 + 1];
            }

            if (ch < 20) {
                const int kb = ch * 8;             // k = 0..159: w in regs
                acc = __fmaf_rn(h0.x, wreg[kb + 0], acc);
                acc = __fmaf_rn(h0.y, wreg[kb + 1], acc);
                acc = __fmaf_rn(h0.z, wreg[kb + 2], acc);
                acc = __fmaf_rn(h0.w, wreg[kb + 3], acc);
                acc = __fmaf_rn(h1.x, wreg[kb + 4], acc);
                acc = __fmaf_rn(h1.y, wreg[kb + 5], acc);
                acc = __fmaf_rn(h1.z, wreg[kb + 6], acc);
                acc = __fmaf_rn(h1.w, wreg[kb + 7], acc);
            } else {                               // k = 160..255: w from smem
                acc = __fmaf_rn(h0.x, w0.x, acc);
                acc = __fmaf_rn(h0.y, w0.y, acc);
                acc = __fmaf_rn(h0.z, w0.z, acc);
                acc = __fmaf_rn(h0.w, w0.w, acc);
                acc = __fmaf_rn(h1.x, w1.x, acc);
                acc = __fmaf_rn(h1.y, w1.y, acc);
                acc = __fmaf_rn(h1.z, w1.z, acc);
                acc = __fmaf_rn(h1.w, w1.w, acc);
                w0 = w2; w1 = w3; w2 = wc; w3 = wd;
            }
            h0 = h2; h1 = h3; h2 = hc; h3 = hd;
        }

        float pre = __fadd_rn(__fadd_rn(xp, acc), bias);
        float h = tanh_xla(pre);

        hnxt[c] = h;
        obase[(size_t)t * DH] = h;

        __syncthreads();

        float* tmp = hcur; hcur = hnxt; hnxt = tmp;
    }
}

// ===========================================================================
extern "C" void kernel_launch(void* const* d_in, const int* in_sizes, int n_in,
                              void* d_out, int out_size)
{
    const float* seq_x  = (const float*)d_in[0];
    const float* Wx     = (const float*)d_in[1];
    const float* bx     = (const float*)d_in[2];
    const float* Wh     = (const float*)d_in[3];
    const float* bh     = (const float*)d_in[4];
    const float* h_init = (const float*)d_in[5];
    float* out = (float*)d_out;

    xproj_kernel<<<dim3(MTOT / 128, DH / 128), 256>>>(seq_x, Wx, bx, out);

    cudaFuncSetAttribute(rnn_rec_kernel,
                         cudaFuncAttributeMaxDynamicSharedMemorySize,
                         REC_SMEM_BYTES);
    rnn_rec_kernel<<<NB, 256, REC_SMEM_BYTES>>>(Wh, bh, h_init, out);
}